// round 11
// baseline (speedup 1.0000x reference)
#include <cuda_runtime.h>
#include <math.h>

#define NB 128
#define NP 8732
#define NM 16
#define NC 21
#define TBLK 128
#define NTIL 69           // ceil(8732/128)

// ---------------- scratch (self-cleaning; static zero-init for first run) ----------------
__device__ float    g_confneg[NB * NP];
__device__ unsigned g_pack[NB * NP];       // (bestv bits & ~0xF) | bestm
__device__ unsigned long long g_best[NB * NM];
__device__ int    g_npos[NB];
__device__ int    g_npos_total;
__device__ double g_loc_sum;
__device__ double g_pos_sum;
__device__ double g_hard_sum;
__device__ int    g_done;

// ---------------- PDL helpers ----------------
__device__ __forceinline__ void pdl_wait() {
    asm volatile("griddepcontrol.wait;" ::: "memory");
}
__device__ __forceinline__ void pdl_trigger() {
    asm volatile("griddepcontrol.launch_dependents;" ::: "memory");
}

// ---------------- numeric helpers ----------------
__device__ __forceinline__ float ce_lse(const float* sv) {
    float mx = sv[0];
    #pragma unroll
    for (int c = 1; c < NC; c++) mx = fmaxf(mx, sv[c]);
    float se = 0.0f;
    #pragma unroll
    for (int c = 0; c < NC; c++) se += __expf(sv[c] - mx);
    return __logf(se) + mx;
}

__device__ __forceinline__ float loc_l1(float4 bx, float4 pr, float4 pl) {
    float cx = 0.5f * (bx.x + bx.z);
    float cy = 0.5f * (bx.y + bx.w);
    float cw = bx.z - bx.x;
    float ch = bx.w - bx.y;
    float g0 = (cx - pr.x) * 10.0f / pr.z;
    float g1 = (cy - pr.y) * 10.0f / pr.w;
    float g2 = __logf(cw / pr.z) * 5.0f;
    float g3 = __logf(ch / pr.w) * 5.0f;
    return fabsf(pl.x - g0) + fabsf(pl.y - g1) + fabsf(pl.z - g2) + fabsf(pl.w - g3);
}

// ================= K1: block-specialized CE (x<69) + match (x>=69) =================
__global__ void __launch_bounds__(TBLK) k1_kernel(
        const float*  __restrict__ scores,
        const float4* __restrict__ boxes,
        const float4* __restrict__ priors) {
    __shared__ float ssc[TBLK * NC];              // CE branch (10.75 KB)
    __shared__ float4 sbox[NM];                   // match branch
    __shared__ float  sarea[NM];
    __shared__ unsigned long long swarp[NM][4];

    int b = blockIdx.y;
    int tid = threadIdx.x;
    int lane = tid & 31, warp = tid >> 5;

    if (blockIdx.x < NTIL) {
        // ---------------- CE branch: conf0 = lse - sv[0] for 128 priors ----------------
        int base = blockIdx.x * TBLK;
        int nval = NP - base; if (nval > TBLK) nval = TBLK;
        const float4* src = (const float4*)(scores + ((size_t)b * NP + base) * NC);
        int nvec = (nval * NC) >> 2;              // (nval*21) % 4 == 0, base 16B-aligned
        for (int i = tid; i < nvec; i += TBLK) {
            unsigned sa = (unsigned)__cvta_generic_to_shared(&((float4*)ssc)[i]);
            asm volatile("cp.async.cg.shared.global [%0], [%1], 16;" :: "r"(sa), "l"(src + i));
        }
        asm volatile("cp.async.commit_group;");
        asm volatile("cp.async.wait_group 0;");
        __syncthreads();
        if (tid < nval) {
            const float* sv = ssc + tid * NC;     // stride 21: conflict-free
            g_confneg[b * NP + base + tid] = ce_lse(sv) - sv[0];
        }
        __syncthreads();
        pdl_trigger();
    } else {
        // ---------------- match branch: 16 IoUs, per-prior best, per-object argmax ----------------
        int base = (blockIdx.x - NTIL) * TBLK;
        int nval = NP - base; if (nval > TBLK) nval = TBLK;

        if (tid < NM) {
            float4 bx = __ldg(&boxes[b * NM + tid]);
            sbox[tid] = bx;
            sarea[tid] = (bx.z - bx.x) * (bx.w - bx.y);
        }
        if (tid < NM * 4) ((unsigned long long*)swarp)[tid] = 0ull;
        __syncthreads();

        int p = base + tid;
        bool valid = (tid < nval);
        unsigned vmask = __ballot_sync(0xFFFFFFFFu, valid);

        float bestv = -1.0f;
        int   bestm = 0;
        float4 pr = make_float4(0.f, 0.f, 1.f, 1.f);
        if (valid) pr = __ldg(&priors[p]);
        {
            float px1 = pr.x - 0.5f * pr.z;
            float py1 = pr.y - 0.5f * pr.w;
            float px2 = pr.x + 0.5f * pr.z;
            float py2 = pr.y + 0.5f * pr.w;
            float pa  = pr.z * pr.w;
            #pragma unroll
            for (int m = 0; m < NM; m++) {
                float iou = 0.0f;
                if (valid) {
                    float4 bx = sbox[m];
                    float lx = fmaxf(bx.x, px1), ly = fmaxf(bx.y, py1);
                    float rx = fminf(bx.z, px2), ry = fminf(bx.w, py2);
                    float w = fmaxf(rx - lx, 0.0f), h = fmaxf(ry - ly, 0.0f);
                    float inter = w * h;
                    iou = __fdividef(inter, sarea[m] + pa - inter);
                }
                if (iou > bestv) { bestv = iou; bestm = m; }  // strict >: lowest m on ties

                // warp argmax over p: REDUX + ballot; winner = lowest lane = lowest p
                unsigned key = valid ? __float_as_uint(iou) : 0u;
                unsigned wmax = __reduce_max_sync(0xFFFFFFFFu, key);
                unsigned ball = __ballot_sync(0xFFFFFFFFu, key == wmax) & vmask;
                if (ball && lane == (int)(__ffs(ball) - 1))
                    swarp[m][warp] = (((unsigned long long)wmax) << 32)
                                   | (unsigned long long)(0xFFFFFFFFu - (unsigned)p);
            }
        }
        if (valid)
            g_pack[b * NP + p] = (__float_as_uint(bestv) & 0xFFFFFFF0u) | (unsigned)bestm;
        __syncthreads();

        if (tid < NM) {
            unsigned long long best = swarp[tid][0];
            #pragma unroll
            for (int w = 1; w < 4; w++)
                if (swarp[tid][w] > best) best = swarp[tid][w];
            if (best) atomicMax(&g_best[b * NM + tid], best);
        }
        __syncthreads();
        pdl_trigger();
    }
}

// ================= K2: positive scan + forced-prior fixup (one block per row) =================
__global__ void __launch_bounds__(256) k2_kernel(
        const float4* __restrict__ plocs,
        const float*  __restrict__ scores,
        const float4* __restrict__ boxes,
        const int*    __restrict__ labels,
        const float4* __restrict__ priors) {
    __shared__ float4 sbox[NM];
    __shared__ int    slab[NM];
    __shared__ float  sl[8], sp[8];
    __shared__ int    sc[8];

    pdl_wait();             // K1's pack/confneg/g_best writes visible
    int b = blockIdx.x;
    int tid = threadIdx.x;
    int lane = tid & 31, warp = tid >> 5;

    if (tid < NM) {
        sbox[tid] = __ldg(&boxes[b * NM + tid]);
        slab[tid] = labels[b * NM + tid];
    }
    __syncthreads();

    // ---- scan: positives are rare (bestv >= 0.5); labels >= 1 so positive <=> bestv >= 0.5 ----
    float possum = 0.0f, locsum = 0.0f;
    int cnt = 0;
    for (int i = tid; i < NP; i += 256) {
        unsigned pk = g_pack[b * NP + i];
        float bv = __uint_as_float(pk & 0xFFFFFFF0u);
        if (!(bv < 0.5f)) {
            int bm = (int)(pk & 0xFu);
            int L  = slab[bm];                     // >= 1
            const float* s = scores + (size_t)(b * NP + i) * NC;
            float sv0 = __ldg(&s[0]);
            float svL = __ldg(&s[L]);
            float conf0 = g_confneg[b * NP + i];
            possum += conf0 + sv0 - svL;           // = lse - sv[L] (assoc-rounded)
            g_confneg[b * NP + i] = 0.0f;          // leaves the negative pool
            locsum += loc_l1(sbox[bm], __ldg(&priors[i]), __ldg(&plocs[b * NP + i]));
            cnt++;
        }
    }
    #pragma unroll
    for (int o = 16; o; o >>= 1) {
        locsum += __shfl_down_sync(0xFFFFFFFFu, locsum, o);
        possum += __shfl_down_sync(0xFFFFFFFFu, possum, o);
        cnt    += __shfl_down_sync(0xFFFFFFFFu, cnt, o);
    }
    if (lane == 0) { sl[warp] = locsum; sp[warp] = possum; sc[warp] = cnt; }
    __syncthreads();   // also orders the scan's confneg global writes within the block

    // ---- warp 0: forced-prior fixup, delta vs the pack-based state the scan used ----
    if (warp == 0) {
        int fp = 0;
        if (lane < NM) {
            unsigned long long kb = atomicExch(&g_best[b * NM + lane], 0ull);
            fp = (kb == 0ull) ? 0
               : (int)(0xFFFFFFFFu - (unsigned)(kb & 0xFFFFFFFFull));
        }
        bool active = (lane < NM);
        #pragma unroll
        for (int o = 0; o < NM; o++) {            // dedupe: last m wins (scatter semantics)
            int po = __shfl_sync(0xFFFFFFFFu, fp, o);
            if (o > lane && po == fp) active = false;
        }
        float d_loc = 0.0f, d_pos = 0.0f;
        int d_np = 0;
        if (active) {
            unsigned pk = g_pack[b * NP + fp];
            float bv = __uint_as_float(pk & 0xFFFFFFF0u);
            int bm = (int)(pk & 0xFu);
            int label_old = (bv < 0.5f) ? 0 : slab[bm];
            int label_new = slab[lane];           // >= 1
            float4 fpr = __ldg(&priors[fp]);
            float4 pl  = __ldg(&plocs[b * NP + fp]);
            float loc_new = loc_l1(sbox[lane], fpr, pl);
            const float* s = scores + (size_t)(b * NP + fp) * NC;
            if (label_old != 0) {
                d_pos = __ldg(&s[label_old]) - __ldg(&s[label_new]);   // conf0+sv0 cancel
                d_loc = loc_new - loc_l1(sbox[bm], fpr, pl);
            } else {
                float conf0 = g_confneg[b * NP + fp];   // untouched by scan (was negative)
                d_pos = conf0 + __ldg(&s[0]) - __ldg(&s[label_new]);
                d_loc = loc_new;
                d_np = 1;
                g_confneg[b * NP + fp] = 0.0f;
            }
        }
        #pragma unroll
        for (int o = 16; o; o >>= 1) {
            d_loc += __shfl_down_sync(0xFFFFFFFFu, d_loc, o);
            d_pos += __shfl_down_sync(0xFFFFFFFFu, d_pos, o);
            d_np  += __shfl_down_sync(0xFFFFFFFFu, d_np, o);
        }
        if (lane == 0) {
            float L = d_loc, Q = d_pos;
            int C = d_np;
            #pragma unroll
            for (int w = 0; w < 8; w++) { L += sl[w]; Q += sp[w]; C += sc[w]; }
            if (L != 0.0f) atomicAdd(&g_loc_sum, (double)L);
            if (Q != 0.0f) atomicAdd(&g_pos_sum, (double)Q);
            g_npos[b] = C;                        // single writer per row
            atomicAdd(&g_npos_total, C);
        }
    }
    __syncthreads();
    pdl_trigger();
}

// ---------------- find_bucket: kth largest bucket (batched-load scan, warp 0 only) ----------------
template <int NBK>
__device__ __forceinline__ void find_bucket(const int* hist, int k, int lane, int* fb) {
    const int chunk = NBK >> 5;
    int base = lane * chunk;
    int cs = 0;
    #pragma unroll
    for (int i = 0; i < chunk; i++) cs += hist[base + i];
    int incl = cs;
    #pragma unroll
    for (int o = 1; o < 32; o <<= 1) {
        int t = __shfl_down_sync(0xFFFFFFFFu, incl, o);
        if (lane + o < 32) incl += t;
    }
    int excl = incl - cs;                       // count in buckets above this chunk
    bool hit = (excl < k) && (k <= incl);
    unsigned ball = __ballot_sync(0xFFFFFFFFu, hit);
    int j = __ffs(ball) - 1;
    if (lane == j) {
        int acc = excl;
        int sel = -1, rem = 0;
        #pragma unroll
        for (int g = 0; g < chunk; g += 8) {
            int h8[8];
            #pragma unroll
            for (int t = 0; t < 8; t++) h8[t] = hist[base + chunk - 1 - (g + t)];
            #pragma unroll
            for (int t = 0; t < 8; t++) {
                if (sel < 0) {
                    int h = h8[t];
                    if (acc + h >= k) { sel = chunk - 1 - (g + t); rem = k - acc; }
                    else acc += h;
                }
            }
        }
        fb[0] = base + sel;
        fb[1] = rem;
    }
}

// ================= K3: hard-negative mining (register-resident) + final combine =================
__global__ void __launch_bounds__(1024, 1) k3_kernel(float* __restrict__ out) {
    __shared__ int hist[2048];
    __shared__ int fb[2];
    __shared__ int s_npos;
    __shared__ double sredd[32];
    __shared__ int sredi[32];

    pdl_wait();             // K2's confneg/npos writes visible
    int b = blockIdx.x;
    int tid = threadIdx.x;
    int lane = tid & 31, warp = tid >> 5;
    const unsigned* cn = (const unsigned*)g_confneg + (size_t)b * NP;

    for (int i = tid; i < 2048; i += 1024) hist[i] = 0;
    if (tid == 0) s_npos = atomicExch(&g_npos[b], 0);     // read + self-clean

    unsigned xv[9];
    #pragma unroll
    for (int j = 0; j < 9; j++) {
        int i = tid + j * 1024;
        xv[j] = (i < NP) ? cn[i] : 0u;
    }
    __syncthreads();

    int k = 3 * s_npos;
    if (k > NP) k = NP;

    // ---- level 1: top 11 bits (sign always 0), warp-aggregated atomics ----
    #pragma unroll
    for (int j = 0; j < 8; j++) {
        unsigned bkt = xv[j] >> 20;
        unsigned mm = __match_any_sync(0xFFFFFFFFu, bkt);
        if ((int)(__ffs(mm) - 1) == lane) atomicAdd(&hist[bkt], __popc(mm));
    }
    if (tid + 8192 < NP) atomicAdd(&hist[xv[8] >> 20], 1);
    __syncthreads();
    if (warp == 0) find_bucket<2048>(hist, k, lane, fb);
    __syncthreads();
    unsigned B1 = (unsigned)fb[0];
    int r = fb[1];
    __syncthreads();
    for (int i = tid; i < 2048; i += 1024) hist[i] = 0;
    __syncthreads();

    // ---- level 2: next 11 bits among bucket B1 ----
    #pragma unroll
    for (int j = 0; j < 9; j++) {
        int i = tid + j * 1024;
        unsigned x = xv[j];
        if (i < NP && (x >> 20) == B1) atomicAdd(&hist[(x >> 9) & 0x7FFu], 1);
    }
    __syncthreads();
    if (warp == 0) find_bucket<2048>(hist, r, lane, fb);
    __syncthreads();
    unsigned pfx = (B1 << 11) | (unsigned)fb[0];
    int r2 = fb[1];
    __syncthreads();
    for (int i = tid; i < 512; i += 1024) hist[i] = 0;
    __syncthreads();

    // ---- level 3: low 9 bits among prefix pfx ----
    #pragma unroll
    for (int j = 0; j < 9; j++) {
        int i = tid + j * 1024;
        unsigned x = xv[j];
        if (i < NP && (x >> 9) == pfx) atomicAdd(&hist[x & 0x1FFu], 1);
    }
    __syncthreads();
    if (warp == 0) find_bucket<512>(hist, r2, lane, fb);
    __syncthreads();
    unsigned thr = (pfx << 9) | (unsigned)fb[0];   // exact kth-largest bit pattern

    // ---- exact top-k sum: strictly greater + tie copies of thr ----
    float s = 0.0f;
    int c = 0;
    #pragma unroll
    for (int j = 0; j < 9; j++) {
        int i = tid + j * 1024;
        unsigned x = xv[j];
        if (i < NP && x > thr) { s += __uint_as_float(x); c++; }
    }
    double sd = (double)s;
    #pragma unroll
    for (int o = 16; o; o >>= 1) {
        sd += __shfl_down_sync(0xFFFFFFFFu, sd, o);
        c  += __shfl_down_sync(0xFFFFFFFFu, c, o);
    }
    if (lane == 0) { sredd[warp] = sd; sredi[warp] = c; }
    __syncthreads();
    if (warp == 0) {
        double S = sredd[lane];
        int C = sredi[lane];
        #pragma unroll
        for (int o = 16; o; o >>= 1) {
            S += __shfl_down_sync(0xFFFFFFFFu, S, o);
            C += __shfl_down_sync(0xFFFFFFFFu, C, o);
        }
        if (lane == 0) {
            atomicAdd(&g_hard_sum, S + (double)(k - C) * (double)__uint_as_float(thr));
            __threadfence();
            if (atomicAdd(&g_done, 1) == NB - 1) {
                __threadfence();
                int nt = atomicAdd(&g_npos_total, 0);
                double hs = atomicAdd(&g_hard_sum, 0.0);
                double ps = atomicAdd(&g_pos_sum, 0.0);
                double ls = atomicAdd(&g_loc_sum, 0.0);
                double conf_loss = (hs + ps) / (double)nt;
                long long dd = 4LL * (long long)nt;
                if (dd < 1) dd = 1;
                out[0] = (float)(conf_loss + ls / (double)dd);
                g_npos_total = 0;
                g_loc_sum = 0.0;
                g_pos_sum = 0.0;
                g_hard_sum = 0.0;
                g_done = 0;
            }
        }
    }
}

// ---------------- launch: 3 kernels, PDL-chained ----------------
extern "C" void kernel_launch(void* const* d_in, const int* in_sizes, int n_in,
                              void* d_out, int out_size) {
    const float4* plocs  = (const float4*)d_in[0];  // [B,P,4]
    const float*  scores = (const float*)d_in[1];   // [B,P,C]
    const float4* boxes  = (const float4*)d_in[2];  // [B,M,4]
    const int*    labels = (const int*)d_in[3];     // [B,M]
    const float4* priors = (const float4*)d_in[4];  // [P,4]
    float* out = (float*)d_out;

    dim3 g1(2 * NTIL, NB);
    k1_kernel<<<g1, TBLK>>>(scores, boxes, priors);

    cudaLaunchAttribute attr[1];
    attr[0].id = cudaLaunchAttributeProgrammaticStreamSerialization;
    attr[0].val.programmaticStreamSerializationAllowed = 1;

    {
        cudaLaunchConfig_t cfg = {};
        cfg.gridDim = dim3(NB);
        cfg.blockDim = dim3(256);
        cfg.attrs = attr;
        cfg.numAttrs = 1;
        cfg.stream = 0;
        cudaLaunchKernelEx(&cfg, k2_kernel, plocs, scores, boxes, labels, priors);
    }
    {
        cudaLaunchConfig_t cfg = {};
        cfg.gridDim = dim3(NB);
        cfg.blockDim = dim3(1024);
        cfg.attrs = attr;
        cfg.numAttrs = 1;
        cfg.stream = 0;
        cudaLaunchKernelEx(&cfg, k3_kernel, out);
    }
}

// round 12
// speedup vs baseline: 1.6387x; 1.6387x over previous
#include <cuda_runtime.h>
#include <math.h>

#define NB 128
#define NP 8732
#define NM 16
#define NC 21
#define TBLK 128
#define NTIL 69           // ceil(8732/128)

// ---------------- scratch (self-cleaning; static zero-init for first run) ----------------
__device__ float    g_confneg[NB * NP];    // conf0 = lse - sv[0], ALL priors (K1 rewrites fully)
__device__ unsigned g_pack[NB * NP];       // (bestv bits & ~0xF) | bestm (K1 rewrites fully)
__device__ unsigned long long g_best[NB * NM];
__device__ int    g_npos_total;
__device__ double g_loc_sum;
__device__ double g_pos_sum;
__device__ double g_hard_sum;
__device__ int    g_done;

// ---------------- PDL helpers ----------------
__device__ __forceinline__ void pdl_wait() {
    asm volatile("griddepcontrol.wait;" ::: "memory");
}
__device__ __forceinline__ void pdl_trigger() {
    asm volatile("griddepcontrol.launch_dependents;" ::: "memory");
}

// ---------------- numeric helpers ----------------
__device__ __forceinline__ float ce_lse(const float* sv) {
    float mx = sv[0];
    #pragma unroll
    for (int c = 1; c < NC; c++) mx = fmaxf(mx, sv[c]);
    float se = 0.0f;
    #pragma unroll
    for (int c = 0; c < NC; c++) se += __expf(sv[c] - mx);
    return __logf(se) + mx;
}

__device__ __forceinline__ float loc_l1(float4 bx, float4 pr, float4 pl) {
    float cx = 0.5f * (bx.x + bx.z);
    float cy = 0.5f * (bx.y + bx.w);
    float cw = bx.z - bx.x;
    float ch = bx.w - bx.y;
    float g0 = (cx - pr.x) * 10.0f / pr.z;
    float g1 = (cy - pr.y) * 10.0f / pr.w;
    float g2 = __logf(cw / pr.z) * 5.0f;
    float g3 = __logf(ch / pr.w) * 5.0f;
    return fabsf(pl.x - g0) + fabsf(pl.y - g1) + fabsf(pl.z - g2) + fabsf(pl.w - g3);
}

// ================= K1: block-specialized CE (x<69) + match (x>=69) — R11-measured 40.5us =================
__global__ void __launch_bounds__(TBLK) k1_kernel(
        const float*  __restrict__ scores,
        const float4* __restrict__ boxes,
        const float4* __restrict__ priors) {
    __shared__ float ssc[TBLK * NC];              // CE branch (10.75 KB)
    __shared__ float4 sbox[NM];                   // match branch
    __shared__ float  sarea[NM];
    __shared__ unsigned long long swarp[NM][4];

    int b = blockIdx.y;
    int tid = threadIdx.x;
    int lane = tid & 31, warp = tid >> 5;

    if (blockIdx.x < NTIL) {
        // ---------------- CE branch: conf0 = lse - sv[0] for 128 priors ----------------
        int base = blockIdx.x * TBLK;
        int nval = NP - base; if (nval > TBLK) nval = TBLK;
        const float4* src = (const float4*)(scores + ((size_t)b * NP + base) * NC);
        int nvec = (nval * NC) >> 2;              // (nval*21) % 4 == 0, base 16B-aligned
        for (int i = tid; i < nvec; i += TBLK) {
            unsigned sa = (unsigned)__cvta_generic_to_shared(&((float4*)ssc)[i]);
            asm volatile("cp.async.cg.shared.global [%0], [%1], 16;" :: "r"(sa), "l"(src + i));
        }
        asm volatile("cp.async.commit_group;");
        asm volatile("cp.async.wait_group 0;");
        __syncthreads();
        if (tid < nval) {
            const float* sv = ssc + tid * NC;     // stride 21: conflict-free
            g_confneg[b * NP + base + tid] = ce_lse(sv) - sv[0];
        }
        __syncthreads();
        pdl_trigger();
    } else {
        // ---------------- match branch: 16 IoUs, per-prior best, per-object argmax ----------------
        int base = (blockIdx.x - NTIL) * TBLK;
        int nval = NP - base; if (nval > TBLK) nval = TBLK;

        if (tid < NM) {
            float4 bx = __ldg(&boxes[b * NM + tid]);
            sbox[tid] = bx;
            sarea[tid] = (bx.z - bx.x) * (bx.w - bx.y);
        }
        if (tid < NM * 4) ((unsigned long long*)swarp)[tid] = 0ull;
        __syncthreads();

        int p = base + tid;
        bool valid = (tid < nval);
        unsigned vmask = __ballot_sync(0xFFFFFFFFu, valid);

        float bestv = -1.0f;
        int   bestm = 0;
        float4 pr = make_float4(0.f, 0.f, 1.f, 1.f);
        if (valid) pr = __ldg(&priors[p]);
        {
            float px1 = pr.x - 0.5f * pr.z;
            float py1 = pr.y - 0.5f * pr.w;
            float px2 = pr.x + 0.5f * pr.z;
            float py2 = pr.y + 0.5f * pr.w;
            float pa  = pr.z * pr.w;
            #pragma unroll
            for (int m = 0; m < NM; m++) {
                float iou = 0.0f;
                if (valid) {
                    float4 bx = sbox[m];
                    float lx = fmaxf(bx.x, px1), ly = fmaxf(bx.y, py1);
                    float rx = fminf(bx.z, px2), ry = fminf(bx.w, py2);
                    float w = fmaxf(rx - lx, 0.0f), h = fmaxf(ry - ly, 0.0f);
                    float inter = w * h;
                    iou = __fdividef(inter, sarea[m] + pa - inter);
                }
                if (iou > bestv) { bestv = iou; bestm = m; }  // strict >: lowest m on ties

                // warp argmax over p: REDUX + ballot; winner = lowest lane = lowest p
                unsigned key = valid ? __float_as_uint(iou) : 0u;
                unsigned wmax = __reduce_max_sync(0xFFFFFFFFu, key);
                unsigned ball = __ballot_sync(0xFFFFFFFFu, key == wmax) & vmask;
                if (ball && lane == (int)(__ffs(ball) - 1))
                    swarp[m][warp] = (((unsigned long long)wmax) << 32)
                                   | (unsigned long long)(0xFFFFFFFFu - (unsigned)p);
            }
        }
        if (valid)
            g_pack[b * NP + p] = (__float_as_uint(bestv) & 0xFFFFFFF0u) | (unsigned)bestm;
        __syncthreads();

        if (tid < NM) {
            unsigned long long best = swarp[tid][0];
            #pragma unroll
            for (int w = 1; w < 4; w++)
                if (swarp[tid][w] > best) best = swarp[tid][w];
            if (best) atomicMax(&g_best[b * NM + tid], best);
        }
        __syncthreads();
        pdl_trigger();
    }
}

// ---------------- find_bucket: kth largest bucket (batched-load scan, warp 0 only) ----------------
template <int NBK>
__device__ __forceinline__ void find_bucket(const int* hist, int k, int lane, int* fb) {
    const int chunk = NBK >> 5;
    int base = lane * chunk;
    int cs = 0;
    #pragma unroll
    for (int i = 0; i < chunk; i++) cs += hist[base + i];
    int incl = cs;
    #pragma unroll
    for (int o = 1; o < 32; o <<= 1) {
        int t = __shfl_down_sync(0xFFFFFFFFu, incl, o);
        if (lane + o < 32) incl += t;
    }
    int excl = incl - cs;                       // count in buckets above this chunk
    bool hit = (excl < k) && (k <= incl);
    unsigned ball = __ballot_sync(0xFFFFFFFFu, hit);
    int j = __ffs(ball) - 1;
    if (lane == j) {
        int acc = excl;
        int sel = -1, rem = 0;
        #pragma unroll
        for (int g = 0; g < chunk; g += 8) {
            int h8[8];
            #pragma unroll
            for (int t = 0; t < 8; t++) h8[t] = hist[base + chunk - 1 - (g + t)];
            #pragma unroll
            for (int t = 0; t < 8; t++) {
                if (sel < 0) {
                    int h = h8[t];
                    if (acc + h >= k) { sel = chunk - 1 - (g + t); rem = k - acc; }
                    else acc += h;
                }
            }
        }
        fb[0] = base + sel;
        fb[1] = rem;
    }
}

// ================= K2: pos-scan + fixup + hard-negative mining + final (one block/row) =================
__global__ void __launch_bounds__(1024, 1) k2_kernel(
        const float4* __restrict__ plocs,
        const float*  __restrict__ scores,
        const float4* __restrict__ boxes,
        const int*    __restrict__ labels,
        const float4* __restrict__ priors,
        float* __restrict__ out) {
    __shared__ int hist[2048];
    __shared__ int fb[2];
    __shared__ int s_npos;
    __shared__ float4 sbox[NM];
    __shared__ int    slab[NM];
    __shared__ int    s_flist[NM];
    __shared__ int    s_fcnt;
    __shared__ float  sl[32], sp[32];
    __shared__ int    sc[32];
    __shared__ double sredd[32];
    __shared__ int    sredi[32];

    pdl_wait();             // K1's pack/confneg/g_best writes visible
    int b = blockIdx.x;
    int tid = threadIdx.x;
    int lane = tid & 31, warp = tid >> 5;
    const unsigned* cn = (const unsigned*)g_confneg + (size_t)b * NP;
    const unsigned* gp = g_pack + (size_t)b * NP;

    if (tid < NM) {
        sbox[tid] = __ldg(&boxes[b * NM + tid]);
        slab[tid] = labels[b * NM + tid];
    }
    for (int i = tid; i < 2048; i += 1024) hist[i] = 0;
    __syncthreads();

    // ---- load register pool + positive scan (positives rare: bv >= 0.5, labels all >= 1) ----
    unsigned xv[9];
    float possum = 0.0f, locsum = 0.0f;
    int cnt = 0;
    #pragma unroll
    for (int j = 0; j < 9; j++) {
        int i = tid + j * 1024;
        unsigned x = 0u, pk = 0u;
        if (i < NP) { x = cn[i]; pk = gp[i]; }
        float bv = __uint_as_float(pk & 0xFFFFFFF0u);
        if (i < NP && !(bv < 0.5f)) {
            int bm = (int)(pk & 0xFu);
            int L  = slab[bm];                    // >= 1
            const float* s = scores + (size_t)(b * NP + i) * NC;
            possum += __uint_as_float(x) + __ldg(&s[0]) - __ldg(&s[L]);  // = lse - sv[L]
            locsum += loc_l1(sbox[bm], __ldg(&priors[i]), __ldg(&plocs[b * NP + i]));
            cnt++;
            x = 0u;                               // leaves the negative pool (registers only)
        }
        xv[j] = x;
    }
    #pragma unroll
    for (int o = 16; o; o >>= 1) {
        locsum += __shfl_down_sync(0xFFFFFFFFu, locsum, o);
        possum += __shfl_down_sync(0xFFFFFFFFu, possum, o);
        cnt    += __shfl_down_sync(0xFFFFFFFFu, cnt, o);
    }
    if (lane == 0) { sl[warp] = locsum; sp[warp] = possum; sc[warp] = cnt; }
    __syncthreads();

    // ---- warp 0: forced-prior fixup (delta vs pack state the scan used) ----
    if (warp == 0) {
        int fp = 0;
        if (lane < NM) {
            unsigned long long kb = atomicExch(&g_best[b * NM + lane], 0ull);
            fp = (kb == 0ull) ? 0
               : (int)(0xFFFFFFFFu - (unsigned)(kb & 0xFFFFFFFFull));
        }
        bool active = (lane < NM);
        #pragma unroll
        for (int o = 0; o < NM; o++) {            // dedupe: last m wins (scatter semantics)
            int po = __shfl_sync(0xFFFFFFFFu, fp, o);
            if (o > lane && po == fp) active = false;
        }
        float d_loc = 0.0f, d_pos = 0.0f;
        int d_np = 0;
        if (active) {
            unsigned pk = gp[fp];
            float bv = __uint_as_float(pk & 0xFFFFFFF0u);
            int bm = (int)(pk & 0xFu);
            int label_old = (bv < 0.5f) ? 0 : slab[bm];
            int label_new = slab[lane];           // >= 1
            float4 fpr = __ldg(&priors[fp]);
            float4 pl  = __ldg(&plocs[b * NP + fp]);
            float loc_new = loc_l1(sbox[lane], fpr, pl);
            const float* s = scores + (size_t)(b * NP + fp) * NC;
            if (label_old != 0) {
                // scan already counted it with label_old; swap label + object
                d_pos = __ldg(&s[label_old]) - __ldg(&s[label_new]);
                d_loc = loc_new - loc_l1(sbox[bm], fpr, pl);
            } else {
                float conf0 = __uint_as_float(cn[fp]);   // global untouched by scan
                d_pos = conf0 + __ldg(&s[0]) - __ldg(&s[label_new]);
                d_loc = loc_new;
                d_np = 1;                          // new positive: patch xv below
            }
        }
        unsigned fm = __ballot_sync(0xFFFFFFFFu, d_np != 0);
        if (d_np) s_flist[__popc(fm & ((1u << lane) - 1))] = fp;
        #pragma unroll
        for (int o = 16; o; o >>= 1) {
            d_loc += __shfl_down_sync(0xFFFFFFFFu, d_loc, o);
            d_pos += __shfl_down_sync(0xFFFFFFFFu, d_pos, o);
            d_np  += __shfl_down_sync(0xFFFFFFFFu, d_np, o);
        }
        if (lane == 0) {
            s_fcnt = __popc(fm);
            float L = d_loc, Q = d_pos;
            int C = d_np;
            #pragma unroll
            for (int w = 0; w < 32; w++) { L += sl[w]; Q += sp[w]; C += sc[w]; }
            if (L != 0.0f) atomicAdd(&g_loc_sum, (double)L);
            if (Q != 0.0f) atomicAdd(&g_pos_sum, (double)Q);
            atomicAdd(&g_npos_total, C);
            s_npos = C;
        }
    }
    __syncthreads();

    // patch forced new-positives out of the register-resident negative pool
    {
        int fcnt = s_fcnt;
        for (int e = 0; e < fcnt; e++) {
            int fp = s_flist[e];
            if ((fp & 1023) == tid) xv[fp >> 10] = 0u;
        }
    }
    __syncthreads();

    int k = 3 * s_npos;
    if (k > NP) k = NP;

    // ---- level 1: top 11 bits (sign always 0), warp-aggregated atomics ----
    #pragma unroll
    for (int j = 0; j < 8; j++) {                 // i = tid + j*1024 < 8192 <= NP: all valid
        unsigned bkt = xv[j] >> 20;
        unsigned mm = __match_any_sync(0xFFFFFFFFu, bkt);
        if ((int)(__ffs(mm) - 1) == lane) atomicAdd(&hist[bkt], __popc(mm));
    }
    if (tid + 8192 < NP) atomicAdd(&hist[xv[8] >> 20], 1);
    __syncthreads();
    if (warp == 0) find_bucket<2048>(hist, k, lane, fb);
    __syncthreads();
    unsigned B1 = (unsigned)fb[0];
    int r = fb[1];
    __syncthreads();
    for (int i = tid; i < 2048; i += 1024) hist[i] = 0;
    __syncthreads();

    // ---- level 2: next 11 bits among bucket B1 ----
    #pragma unroll
    for (int j = 0; j < 9; j++) {
        int i = tid + j * 1024;
        unsigned x = xv[j];
        if (i < NP && (x >> 20) == B1) atomicAdd(&hist[(x >> 9) & 0x7FFu], 1);
    }
    __syncthreads();
    if (warp == 0) find_bucket<2048>(hist, r, lane, fb);
    __syncthreads();
    unsigned pfx = (B1 << 11) | (unsigned)fb[0];
    int r2 = fb[1];
    __syncthreads();
    for (int i = tid; i < 512; i += 1024) hist[i] = 0;
    __syncthreads();

    // ---- level 3: low 9 bits among prefix pfx ----
    #pragma unroll
    for (int j = 0; j < 9; j++) {
        int i = tid + j * 1024;
        unsigned x = xv[j];
        if (i < NP && (x >> 9) == pfx) atomicAdd(&hist[x & 0x1FFu], 1);
    }
    __syncthreads();
    if (warp == 0) find_bucket<512>(hist, r2, lane, fb);
    __syncthreads();
    unsigned thr = (pfx << 9) | (unsigned)fb[0];  // exact kth-largest bit pattern

    // ---- exact top-k sum: strictly greater + tie copies of thr ----
    float s = 0.0f;
    int c = 0;
    #pragma unroll
    for (int j = 0; j < 9; j++) {
        int i = tid + j * 1024;
        unsigned x = xv[j];
        if (i < NP && x > thr) { s += __uint_as_float(x); c++; }
    }
    double sd = (double)s;
    #pragma unroll
    for (int o = 16; o; o >>= 1) {
        sd += __shfl_down_sync(0xFFFFFFFFu, sd, o);
        c  += __shfl_down_sync(0xFFFFFFFFu, c, o);
    }
    if (lane == 0) { sredd[warp] = sd; sredi[warp] = c; }
    __syncthreads();
    if (warp == 0) {
        double S = sredd[lane];
        int C = sredi[lane];
        #pragma unroll
        for (int o = 16; o; o >>= 1) {
            S += __shfl_down_sync(0xFFFFFFFFu, S, o);
            C += __shfl_down_sync(0xFFFFFFFFu, C, o);
        }
        if (lane == 0) {
            atomicAdd(&g_hard_sum, S + (double)(k - C) * (double)__uint_as_float(thr));
            __threadfence();
            if (atomicAdd(&g_done, 1) == NB - 1) {
                __threadfence();
                int nt = atomicAdd(&g_npos_total, 0);
                double hs = atomicAdd(&g_hard_sum, 0.0);
                double ps = atomicAdd(&g_pos_sum, 0.0);
                double ls = atomicAdd(&g_loc_sum, 0.0);
                double conf_loss = (hs + ps) / (double)nt;
                long long dd = 4LL * (long long)nt;
                if (dd < 1) dd = 1;
                out[0] = (float)(conf_loss + ls / (double)dd);
                g_npos_total = 0;
                g_loc_sum = 0.0;
                g_pos_sum = 0.0;
                g_hard_sum = 0.0;
                g_done = 0;
            }
        }
    }
}

// ---------------- launch: 2 kernels, PDL-chained ----------------
extern "C" void kernel_launch(void* const* d_in, const int* in_sizes, int n_in,
                              void* d_out, int out_size) {
    const float4* plocs  = (const float4*)d_in[0];  // [B,P,4]
    const float*  scores = (const float*)d_in[1];   // [B,P,C]
    const float4* boxes  = (const float4*)d_in[2];  // [B,M,4]
    const int*    labels = (const int*)d_in[3];     // [B,M]
    const float4* priors = (const float4*)d_in[4];  // [P,4]
    float* out = (float*)d_out;

    dim3 g1(2 * NTIL, NB);
    k1_kernel<<<g1, TBLK>>>(scores, boxes, priors);

    cudaLaunchAttribute attr[1];
    attr[0].id = cudaLaunchAttributeProgrammaticStreamSerialization;
    attr[0].val.programmaticStreamSerializationAllowed = 1;

    cudaLaunchConfig_t cfg = {};
    cfg.gridDim = dim3(NB);
    cfg.blockDim = dim3(1024);
    cfg.attrs = attr;
    cfg.numAttrs = 1;
    cfg.stream = 0;
    cudaLaunchKernelEx(&cfg, k2_kernel, plocs, scores, boxes, labels, priors, out);
}